// round 1
// baseline (speedup 1.0000x reference)
#include <cuda_runtime.h>
#include <math.h>

#define BATCH 64
#define E 128
#define NSEQ 1024
#define NHEADS 8
#define DH 16
#define DFF 512
#define MROWS (BATCH * NSEQ)   // 65536
#define NLAYERS 4
#define LN_EPS 1e-5f

// ---------------- scratch (static device globals; allocation-free) ----------
__device__ float g_t[MROWS * E];      // residual stream (B, N, E)
__device__ float g_y[MROWS * E];      // layernorm output
__device__ float g_q[MROWS * E];
__device__ float g_k[MROWS * E];
__device__ float g_v[MROWS * E];
__device__ float g_o[MROWS * E];
__device__ float g_ctx[BATCH * NHEADS * DH * DH];
__device__ float g_ff[MROWS * DFF];

// ---------------- transpose x:(B,E,N) -> t:(B,N,E) --------------------------
__global__ void transpose_kernel(const float* __restrict__ x) {
    __shared__ float tile[32][33];
    int b  = blockIdx.z;
    int n0 = blockIdx.x * 32;
    int e0 = blockIdx.y * 32;
    int tx = threadIdx.x, ty = threadIdx.y;   // (32,8)
#pragma unroll
    for (int i = 0; i < 32; i += 8)
        tile[ty + i][tx] = x[(size_t)b * E * NSEQ + (size_t)(e0 + ty + i) * NSEQ + n0 + tx];
    __syncthreads();
#pragma unroll
    for (int i = 0; i < 32; i += 8)
        g_t[(size_t)b * NSEQ * E + (size_t)(n0 + ty + i) * E + e0 + tx] = tile[tx][ty + i];
}

// ---------------- layernorm over E=128 (one block of 128 threads per row) ---
__global__ void ln_kernel(const float* __restrict__ gamma, const float* __restrict__ beta) {
    int m = blockIdx.x;
    int e = threadIdx.x;
    float v = g_t[(size_t)m * E + e];

    __shared__ float red[4];
    float s = v;
#pragma unroll
    for (int o = 16; o > 0; o >>= 1) s += __shfl_down_sync(0xffffffffu, s, o);
    if ((e & 31) == 0) red[e >> 5] = s;
    __syncthreads();
    float mu = (red[0] + red[1] + red[2] + red[3]) * (1.0f / E);
    __syncthreads();

    float d = v - mu;
    float s2 = d * d;
#pragma unroll
    for (int o = 16; o > 0; o >>= 1) s2 += __shfl_down_sync(0xffffffffu, s2, o);
    if ((e & 31) == 0) red[e >> 5] = s2;
    __syncthreads();
    float var = (red[0] + red[1] + red[2] + red[3]) * (1.0f / E);

    g_y[(size_t)m * E + e] = d * rsqrtf(var + LN_EPS) * gamma[e] + beta[e];
}

// ---------------- generic tiled fp32 GEMM -----------------------------------
// C[M,N] = op(A[M,K] @ W[K,N] + bias) (+ C if residual flag)
// flags: bit0 = gelu, bit1 = residual add into C
#define BM 64
#define BN 64
#define BK 16

__device__ __forceinline__ float gelu_f(float x) {
    float x3 = x * x * x;
    return 0.5f * x * (1.0f + tanhf(0.7978845608028654f * (x + 0.044715f * x3)));
}

__global__ void gemm_kernel(const float* __restrict__ A, const float* __restrict__ W,
                            const float* __restrict__ bias, float* __restrict__ C,
                            int K, int N, int flags) {
    __shared__ float As[BK][BM + 1];
    __shared__ float Ws[BK][BN];
    int bm = blockIdx.y * BM;
    int bn = blockIdx.x * BN;
    int tx = threadIdx.x & 15;     // 0..15
    int ty = threadIdx.x >> 4;     // 0..15

    float acc[4][4] = {};
    for (int k0 = 0; k0 < K; k0 += BK) {
        for (int l = threadIdx.x; l < BM * BK; l += 256) {
            int r = l >> 4, c = l & 15;
            As[c][r] = A[(size_t)(bm + r) * K + k0 + c];
        }
        for (int l = threadIdx.x; l < BK * BN; l += 256) {
            int r = l >> 6, c = l & 63;
            Ws[r][c] = W[(size_t)(k0 + r) * N + bn + c];
        }
        __syncthreads();
#pragma unroll
        for (int kk = 0; kk < BK; kk++) {
            float a[4], w[4];
#pragma unroll
            for (int i = 0; i < 4; i++) a[i] = As[kk][ty * 4 + i];
#pragma unroll
            for (int j = 0; j < 4; j++) w[j] = Ws[kk][tx * 4 + j];
#pragma unroll
            for (int i = 0; i < 4; i++)
#pragma unroll
                for (int j = 0; j < 4; j++) acc[i][j] += a[i] * w[j];
        }
        __syncthreads();
    }

#pragma unroll
    for (int i = 0; i < 4; i++) {
        int m = bm + ty * 4 + i;
#pragma unroll
        for (int j = 0; j < 4; j++) {
            int n = bn + tx * 4 + j;
            float v = acc[i][j];
            if (bias) v += bias[n];
            if (flags & 1) v = gelu_f(v);
            size_t idx = (size_t)m * N + n;
            if (flags & 2) C[idx] += v;
            else           C[idx] = v;
        }
    }
}

// ---------------- softmax over feature dim (dh=16) for q, scaled ------------
__global__ void softmax_q_kernel() {
    int idx = blockIdx.x * 256 + threadIdx.x;   // (m, h)
    int m = idx >> 3, h = idx & 7;
    float* p = g_q + (size_t)m * E + h * DH;
    float vals[DH];
    float mx = -1e30f;
#pragma unroll
    for (int d = 0; d < DH; d++) { vals[d] = p[d]; mx = fmaxf(mx, vals[d]); }
    float s = 0.f;
#pragma unroll
    for (int d = 0; d < DH; d++) { vals[d] = expf(vals[d] - mx); s += vals[d]; }
    float r = 0.25f / s;   // dh^-0.5 = 16^-0.5 = 0.25
#pragma unroll
    for (int d = 0; d < DH; d++) p[d] = vals[d] * r;
}

// ---------------- softmax over sequence dim (N=1024) for k ------------------
// one block per (b, column) where column = h*16+d spans all E=128 columns
__global__ void softmax_k_kernel() {
    int bcol = blockIdx.x;            // b*128 + col
    int b = bcol >> 7, col = bcol & 127;
    size_t base = (size_t)b * NSEQ * E + col;
    int tid = threadIdx.x;            // 256 threads, 4 elems each
    float vals[4];
    float mx = -1e30f;
#pragma unroll
    for (int i = 0; i < 4; i++) {
        vals[i] = g_k[base + (size_t)(tid + i * 256) * E];
        mx = fmaxf(mx, vals[i]);
    }
    __shared__ float redm[8], reds[8];
    int lane = tid & 31, warp = tid >> 5;
    float m = mx;
#pragma unroll
    for (int o = 16; o > 0; o >>= 1) m = fmaxf(m, __shfl_down_sync(0xffffffffu, m, o));
    if (lane == 0) redm[warp] = m;
    __syncthreads();
    if (tid == 0) {
        float t = redm[0];
        for (int i = 1; i < 8; i++) t = fmaxf(t, redm[i]);
        redm[0] = t;
    }
    __syncthreads();
    float bm = redm[0];

    float s = 0.f;
#pragma unroll
    for (int i = 0; i < 4; i++) { vals[i] = expf(vals[i] - bm); s += vals[i]; }
#pragma unroll
    for (int o = 16; o > 0; o >>= 1) s += __shfl_down_sync(0xffffffffu, s, o);
    if (lane == 0) reds[warp] = s;
    __syncthreads();
    if (tid == 0) {
        float t = 0.f;
        for (int i = 0; i < 8; i++) t += reds[i];
        reds[0] = t;
    }
    __syncthreads();
    float inv = 1.0f / reds[0];
#pragma unroll
    for (int i = 0; i < 4; i++)
        g_k[base + (size_t)(tid + i * 256) * E] = vals[i] * inv;
}

// ---------------- ctx = k^T v per (b,h): 16x16, K=1024 ----------------------
__global__ void ctx_kernel() {
    int bh = blockIdx.x;              // b*8 + h
    int b = bh >> 3, h = bh & 7;
    int d = threadIdx.x >> 4, e = threadIdx.x & 15;
    __shared__ float ks[128][DH];
    __shared__ float vs[128][DH];
    const float* kp = g_k + (size_t)b * NSEQ * E + h * DH;
    const float* vp = g_v + (size_t)b * NSEQ * E + h * DH;
    float acc = 0.f;
    for (int n0 = 0; n0 < NSEQ; n0 += 128) {
        for (int l = threadIdx.x; l < 128 * DH; l += 256) {
            int nl = l >> 4, c = l & 15;
            ks[nl][c] = kp[(size_t)(n0 + nl) * E + c];
            vs[nl][c] = vp[(size_t)(n0 + nl) * E + c];
        }
        __syncthreads();
#pragma unroll
        for (int nl = 0; nl < 128; nl++) acc += ks[nl][d] * vs[nl][e];
        __syncthreads();
    }
    g_ctx[bh * 256 + d * 16 + e] = acc;
}

// ---------------- o = q @ ctx ------------------------------------------------
__global__ void attn_o_kernel() {
    int m = blockIdx.x;
    int e = threadIdx.x;              // 0..127
    int h = e >> 4, el = e & 15;
    int b = m >> 10;
    const float* qp = g_q + (size_t)m * E + h * DH;
    const float* cp = g_ctx + (b * NHEADS + h) * 256 + el;
    float acc = 0.f;
#pragma unroll
    for (int d = 0; d < DH; d++) acc += qp[d] * cp[d * 16];
    g_o[(size_t)m * E + e] = acc;
}

// ---------------- final mean over sequence ----------------------------------
__global__ void mean_kernel(float* __restrict__ out) {
    int b = blockIdx.x, e = threadIdx.x;
    const float* p = g_t + (size_t)b * NSEQ * E + e;
    float s = 0.f;
    for (int n = 0; n < NSEQ; n++) s += p[(size_t)n * E];
    out[b * E + e] = s * (1.0f / NSEQ);
}

// ---------------- launch -----------------------------------------------------
extern "C" void kernel_launch(void* const* d_in, const int* in_sizes, int n_in,
                              void* d_out, int out_size) {
    const float* x     = (const float*)d_in[0];
    const float* q_w   = (const float*)d_in[1];
    const float* k_w   = (const float*)d_in[2];
    const float* v_w   = (const float*)d_in[3];
    const float* o_w   = (const float*)d_in[4];
    const float* o_b   = (const float*)d_in[5];
    const float* ln1_g = (const float*)d_in[6];
    const float* ln1_b = (const float*)d_in[7];
    const float* ff_w1 = (const float*)d_in[8];
    const float* ff_b1 = (const float*)d_in[9];
    const float* ff_w2 = (const float*)d_in[10];
    const float* ff_b2 = (const float*)d_in[11];
    const float* ln2_g = (const float*)d_in[12];
    const float* ln2_b = (const float*)d_in[13];
    float* out = (float*)d_out;

    float *pt, *py, *pq, *pk, *pv, *po, *pff;
    cudaGetSymbolAddress((void**)&pt,  g_t);
    cudaGetSymbolAddress((void**)&py,  g_y);
    cudaGetSymbolAddress((void**)&pq,  g_q);
    cudaGetSymbolAddress((void**)&pk,  g_k);
    cudaGetSymbolAddress((void**)&pv,  g_v);
    cudaGetSymbolAddress((void**)&po,  g_o);
    cudaGetSymbolAddress((void**)&pff, g_ff);

    transpose_kernel<<<dim3(NSEQ / 32, E / 32, BATCH), dim3(32, 8)>>>(x);

    dim3 gemm_block(256);
    for (int i = 0; i < NLAYERS; i++) {
        // --- attention block ---
        ln_kernel<<<MROWS, E>>>(ln1_g + i * E, ln1_b + i * E);
        gemm_kernel<<<dim3(E / BN, MROWS / BM), gemm_block>>>(py, q_w + i * E * E, nullptr, pq, E, E, 0);
        gemm_kernel<<<dim3(E / BN, MROWS / BM), gemm_block>>>(py, k_w + i * E * E, nullptr, pk, E, E, 0);
        gemm_kernel<<<dim3(E / BN, MROWS / BM), gemm_block>>>(py, v_w + i * E * E, nullptr, pv, E, E, 0);
        softmax_q_kernel<<<(MROWS * NHEADS) / 256, 256>>>();
        softmax_k_kernel<<<BATCH * E, 256>>>();
        ctx_kernel<<<BATCH * NHEADS, 256>>>();
        attn_o_kernel<<<MROWS, E>>>();
        gemm_kernel<<<dim3(E / BN, MROWS / BM), gemm_block>>>(po, o_w + i * E * E, o_b + i * E, pt, E, E, 2);
        // --- feed-forward block ---
        ln_kernel<<<MROWS, E>>>(ln2_g + i * E, ln2_b + i * E);
        gemm_kernel<<<dim3(DFF / BN, MROWS / BM), gemm_block>>>(py, ff_w1 + i * E * DFF, ff_b1 + i * DFF, pff, E, DFF, 1);
        gemm_kernel<<<dim3(E / BN, MROWS / BM), gemm_block>>>(pff, ff_w2 + i * DFF * E, ff_b2 + i * E, pt, DFF, E, 2);
    }

    mean_kernel<<<BATCH, E>>>(out);
}

// round 2
// speedup vs baseline: 2.6826x; 2.6826x over previous
#include <cuda_runtime.h>
#include <math.h>
#include <stdint.h>

#define BATCH 64
#define E 128
#define NSEQ 1024
#define NHEADS 8
#define DH 16
#define DFF 512
#define MROWS (BATCH * NSEQ)   // 65536
#define NLAYERS 4
#define LN_EPS 1e-5f

// ---------------- scratch (static device globals; allocation-free) ----------
__device__ float g_t[MROWS * E];      // residual stream (B, N, E)
__device__ float g_y[MROWS * E];      // layernorm output (tf32-rounded)
__device__ float g_q[MROWS * E];
__device__ float g_k[MROWS * E];
__device__ float g_v[MROWS * E];
__device__ float g_o[MROWS * E];      // tf32-rounded
__device__ float g_ctx[BATCH * NHEADS * DH * DH];
__device__ float g_ff[MROWS * DFF];   // tf32-rounded
// transposed+tf32-rounded weights, per layer: q(16384) k v o, ff1t(65536), ff2t(65536)
#define WT_LAYER 196608
__device__ float g_wt[NLAYERS * WT_LAYER];

__device__ __forceinline__ float rna_tf32(float x) {
    uint32_t u;
    asm("cvt.rna.tf32.f32 %0, %1;" : "=r"(u) : "f"(x));
    return __uint_as_float(u);
}

__device__ __forceinline__ float gelu_f(float x) {
    float x3 = x * x * x;
    return 0.5f * x * (1.0f + tanhf(0.7978845608028654f * (x + 0.044715f * x3)));
}

// ---------------- transpose x:(B,E,N) -> t:(B,N,E) --------------------------
__global__ void transpose_kernel(const float* __restrict__ x) {
    __shared__ float tile[32][33];
    int b  = blockIdx.z;
    int n0 = blockIdx.x * 32;
    int e0 = blockIdx.y * 32;
    int tx = threadIdx.x, ty = threadIdx.y;   // (32,8)
#pragma unroll
    for (int i = 0; i < 32; i += 8)
        tile[ty + i][tx] = x[(size_t)b * E * NSEQ + (size_t)(e0 + ty + i) * NSEQ + n0 + tx];
    __syncthreads();
#pragma unroll
    for (int i = 0; i < 32; i += 8)
        g_t[(size_t)b * NSEQ * E + (size_t)(n0 + ty + i) * E + e0 + tx] = tile[tx][ty + i];
}

// ---------------- weight convert: src[K][N] -> dst[N][K], tf32 rna ----------
__global__ void wt_cvt_kernel(const float* __restrict__ src, float* __restrict__ dst,
                              int K, int N) {
    __shared__ float tile[32][33];
    int n0 = blockIdx.x * 32;
    int k0 = blockIdx.y * 32;
    int tx = threadIdx.x, ty = threadIdx.y;   // (32,8)
#pragma unroll
    for (int i = 0; i < 32; i += 8)
        tile[ty + i][tx] = src[(size_t)(k0 + ty + i) * N + n0 + tx];
    __syncthreads();
#pragma unroll
    for (int i = 0; i < 32; i += 8)
        dst[(size_t)(n0 + ty + i) * K + k0 + tx] = rna_tf32(tile[tx][ty + i]);
}

// ---------------- layernorm over E=128, tf32-rounded output -----------------
__global__ void ln_kernel(const float* __restrict__ gamma, const float* __restrict__ beta) {
    int m = blockIdx.x;
    int e = threadIdx.x;
    float v = g_t[(size_t)m * E + e];

    __shared__ float red[4];
    float s = v;
#pragma unroll
    for (int o = 16; o > 0; o >>= 1) s += __shfl_down_sync(0xffffffffu, s, o);
    if ((e & 31) == 0) red[e >> 5] = s;
    __syncthreads();
    float mu = (red[0] + red[1] + red[2] + red[3]) * (1.0f / E);
    __syncthreads();

    float d = v - mu;
    float s2 = d * d;
#pragma unroll
    for (int o = 16; o > 0; o >>= 1) s2 += __shfl_down_sync(0xffffffffu, s2, o);
    if ((e & 31) == 0) red[e >> 5] = s2;
    __syncthreads();
    float var = (red[0] + red[1] + red[2] + red[3]) * (1.0f / E);

    g_y[(size_t)m * E + e] = rna_tf32(d * rsqrtf(var + LN_EPS) * gamma[e] + beta[e]);
}

// ---------------- TF32 tensor-core GEMM -------------------------------------
// C[M,N] = op(A[M,K] @ Wt[N,K]^T + bias)  (+C if residual)
// flags: bit0=gelu, bit1=residual add, bit2=round output to tf32
// BM=128 BN=128 BK=32, 256 threads, 8 warps (2m x 4n), warp tile 64x32.
#define GBM 128
#define GBN 128
#define GBK 32
#define SMEM_STAGE 16384           // bytes per matrix per stage (128*32*4)
#define SMEM_TOTAL 65536           // 2 stages * (A+B)

#define LDSM4(d0, d1, d2, d3, addr) \
    asm volatile("ldmatrix.sync.aligned.m8n8.x4.shared.b16 {%0,%1,%2,%3}, [%4];" \
                 : "=r"(d0), "=r"(d1), "=r"(d2), "=r"(d3) : "r"(addr))

#define MMA_TF32(c, a, b) \
    asm volatile("mma.sync.aligned.m16n8k8.row.col.f32.tf32.tf32.f32 " \
                 "{%0,%1,%2,%3},{%4,%5,%6,%7},{%8,%9},{%0,%1,%2,%3};" \
                 : "+f"((c)[0]), "+f"((c)[1]), "+f"((c)[2]), "+f"((c)[3]) \
                 : "r"((a)[0]), "r"((a)[1]), "r"((a)[2]), "r"((a)[3]), \
                   "r"((b)[0]), "r"((b)[1]))

__device__ __forceinline__ void cp_async16(uint32_t dst, const void* src) {
    asm volatile("cp.async.cg.shared.global [%0], [%1], 16;" :: "r"(dst), "l"(src));
}

__global__ __launch_bounds__(256, 2) void mma_gemm(
    const float* __restrict__ A, const float* __restrict__ Wt,
    const float* __restrict__ bias, float* __restrict__ C,
    int K, int N, int flags)
{
    extern __shared__ float sm[];
    uint32_t smem_u = (uint32_t)__cvta_generic_to_shared(sm);

    int tid  = threadIdx.x;
    int lane = tid & 31;
    int wid  = tid >> 5;
    int warp_m = wid & 1;            // 0..1 -> 64-row slabs
    int warp_n = wid >> 1;           // 0..3 -> 32-col slabs
    int bm0 = blockIdx.y * GBM;
    int bn0 = blockIdx.x * GBN;

    // global->smem slot geometry (fixed per thread): 1024 16B-chunks per tile
    int r0 = tid >> 3;               // row within first 32
    int c8 = tid & 7;                // 16B chunk within row
    uint32_t cxor = (uint32_t)((c8 ^ (r0 & 7)) << 4);

    // fragment geometry
    int sub = lane >> 3;
    int l7  = lane & 7;
    int selA = sub >> 1;                  // chunk offset for A ldmatrix
    int rowAoff = ((sub & 1) << 3) + l7;  // row offset within 16-row tile
    int selB = sub & 1;
    int rowBoff = ((sub >> 1) << 3) + l7;

    float acc[4][4][4];
#pragma unroll
    for (int i = 0; i < 4; i++)
#pragma unroll
        for (int j = 0; j < 4; j++)
#pragma unroll
            for (int k = 0; k < 4; k++) acc[i][j][k] = 0.f;

    int nIter = K >> 5;

    // ---- tile loader ----
    auto load_tile = [&](int s, int k0) {
#pragma unroll
        for (int i = 0; i < 4; i++) {
            int r = r0 + i * 32;
            uint32_t doff = (uint32_t)(r << 7) + cxor;
            const float* pa = A  + (size_t)(bm0 + r) * K + k0 + c8 * 4;
            const float* pb = Wt + (size_t)(bn0 + r) * K + k0 + c8 * 4;
            cp_async16(smem_u + s * SMEM_STAGE + doff, pa);
            cp_async16(smem_u + 32768 + s * SMEM_STAGE + doff, pb);
        }
    };

    load_tile(0, 0);
    asm volatile("cp.async.commit_group;");

    for (int it = 0; it < nIter; it++) {
        if (it + 1 < nIter) {
            load_tile((it + 1) & 1, (it + 1) * GBK);
            asm volatile("cp.async.commit_group;");
            asm volatile("cp.async.wait_group 1;");
        } else {
            asm volatile("cp.async.wait_group 0;");
        }
        __syncthreads();

        int s = it & 1;
        uint32_t baseA = smem_u + s * SMEM_STAGE;
        uint32_t baseB = smem_u + 32768 + s * SMEM_STAGE;

#pragma unroll
        for (int ks = 0; ks < 4; ks++) {
            int cb = ks * 2;
            uint32_t a[4][4], b[4][2];
#pragma unroll
            for (int mt = 0; mt < 4; mt++) {
                int row = warp_m * 64 + mt * 16 + rowAoff;
                uint32_t addr = baseA + (row << 7) + (uint32_t)(((cb + selA) ^ (row & 7)) << 4);
                LDSM4(a[mt][0], a[mt][1], a[mt][2], a[mt][3], addr);
            }
#pragma unroll
            for (int bt = 0; bt < 2; bt++) {
                int row = warp_n * 32 + bt * 16 + rowBoff;
                uint32_t addr = baseB + (row << 7) + (uint32_t)(((cb + selB) ^ (row & 7)) << 4);
                LDSM4(b[2 * bt][0], b[2 * bt][1], b[2 * bt + 1][0], b[2 * bt + 1][1], addr);
            }
#pragma unroll
            for (int mt = 0; mt < 4; mt++)
#pragma unroll
                for (int nt = 0; nt < 4; nt++)
                    MMA_TF32(acc[mt][nt], a[mt], b[nt]);
        }
        __syncthreads();
    }

    // ---- epilogue ----
    int g  = lane >> 2;
    int t4 = lane & 3;
#pragma unroll
    for (int mt = 0; mt < 4; mt++) {
        int row = bm0 + warp_m * 64 + mt * 16 + g;
#pragma unroll
        for (int nt = 0; nt < 4; nt++) {
            int col = bn0 + warp_n * 32 + nt * 8 + t4 * 2;
            float v00 = acc[mt][nt][0], v01 = acc[mt][nt][1];
            float v10 = acc[mt][nt][2], v11 = acc[mt][nt][3];
            if (bias) {
                float b0 = bias[col], b1 = bias[col + 1];
                v00 += b0; v01 += b1; v10 += b0; v11 += b1;
            }
            if (flags & 1) {
                v00 = gelu_f(v00); v01 = gelu_f(v01);
                v10 = gelu_f(v10); v11 = gelu_f(v11);
            }
            if (flags & 4) {
                v00 = rna_tf32(v00); v01 = rna_tf32(v01);
                v10 = rna_tf32(v10); v11 = rna_tf32(v11);
            }
            float2* p0 = (float2*)(C + (size_t)row * N + col);
            float2* p1 = (float2*)(C + (size_t)(row + 8) * N + col);
            if (flags & 2) {
                float2 o0 = *p0, o1 = *p1;
                o0.x += v00; o0.y += v01; o1.x += v10; o1.y += v11;
                *p0 = o0; *p1 = o1;
            } else {
                *p0 = make_float2(v00, v01);
                *p1 = make_float2(v10, v11);
            }
        }
    }
}

// ---------------- softmax over sequence dim (N=1024) for k ------------------
__global__ void softmax_k_kernel() {
    int bcol = blockIdx.x;            // b*128 + col
    int b = bcol >> 7, col = bcol & 127;
    size_t base = (size_t)b * NSEQ * E + col;
    int tid = threadIdx.x;            // 256 threads, 4 elems each
    float vals[4];
    float mx = -1e30f;
#pragma unroll
    for (int i = 0; i < 4; i++) {
        vals[i] = g_k[base + (size_t)(tid + i * 256) * E];
        mx = fmaxf(mx, vals[i]);
    }
    __shared__ float redm[8], reds[8];
    int lane = tid & 31, warp = tid >> 5;
    float m = mx;
#pragma unroll
    for (int o = 16; o > 0; o >>= 1) m = fmaxf(m, __shfl_down_sync(0xffffffffu, m, o));
    if (lane == 0) redm[warp] = m;
    __syncthreads();
    if (tid == 0) {
        float t = redm[0];
        for (int i = 1; i < 8; i++) t = fmaxf(t, redm[i]);
        redm[0] = t;
    }
    __syncthreads();
    float bm = redm[0];

    float s = 0.f;
#pragma unroll
    for (int i = 0; i < 4; i++) { vals[i] = expf(vals[i] - bm); s += vals[i]; }
#pragma unroll
    for (int o = 16; o > 0; o >>= 1) s += __shfl_down_sync(0xffffffffu, s, o);
    if (lane == 0) reds[warp] = s;
    __syncthreads();
    if (tid == 0) {
        float t = 0.f;
        for (int i = 0; i < 8; i++) t += reds[i];
        reds[0] = t;
    }
    __syncthreads();
    float inv = 1.0f / reds[0];
#pragma unroll
    for (int i = 0; i < 4; i++)
        g_k[base + (size_t)(tid + i * 256) * E] = vals[i] * inv;
}

// ---------------- ctx = k^T v per (b,h): 16x16, K=1024 ----------------------
__global__ void ctx_kernel() {
    int bh = blockIdx.x;              // b*8 + h
    int b = bh >> 3, h = bh & 7;
    int d = threadIdx.x >> 4, e = threadIdx.x & 15;
    __shared__ float ks[128][DH];
    __shared__ float vs[128][DH];
    const float* kp = g_k + (size_t)b * NSEQ * E + h * DH;
    const float* vp = g_v + (size_t)b * NSEQ * E + h * DH;
    float acc = 0.f;
    for (int n0 = 0; n0 < NSEQ; n0 += 128) {
        for (int l = threadIdx.x; l < 128 * DH; l += 256) {
            int nl = l >> 4, c = l & 15;
            ks[nl][c] = kp[(size_t)(n0 + nl) * E + c];
            vs[nl][c] = vp[(size_t)(n0 + nl) * E + c];
        }
        __syncthreads();
#pragma unroll
        for (int nl = 0; nl < 128; nl++) acc += ks[nl][d] * vs[nl][e];
        __syncthreads();
    }
    g_ctx[bh * 256 + d * 16 + e] = acc;
}

// ---------------- o = softmax_q(q) @ ctx (fused), tf32-rounded --------------
__global__ void attn_o_kernel() {
    int m = blockIdx.x;
    int e = threadIdx.x;              // 0..127
    int h = e >> 4, el = e & 15;
    int b = m >> 10;
    const float* qp = g_q + (size_t)m * E + h * DH;
    float qv[DH];
    float mx = -1e30f;
#pragma unroll
    for (int d = 0; d < DH; d++) { qv[d] = qp[d]; mx = fmaxf(mx, qv[d]); }
    float s = 0.f;
#pragma unroll
    for (int d = 0; d < DH; d++) { qv[d] = expf(qv[d] - mx); s += qv[d]; }
    float r = 0.25f / s;   // dh^-0.5 = 0.25
    const float* cp = g_ctx + (b * NHEADS + h) * 256 + el;
    float acc = 0.f;
#pragma unroll
    for (int d = 0; d < DH; d++) acc += qv[d] * cp[d * 16];
    g_o[(size_t)m * E + e] = rna_tf32(acc * r);
}

// ---------------- final mean over sequence ----------------------------------
__global__ void mean_kernel(float* __restrict__ out) {
    int b = blockIdx.x, e = threadIdx.x;
    const float* p = g_t + (size_t)b * NSEQ * E + e;
    float s = 0.f;
    for (int n = 0; n < NSEQ; n++) s += p[(size_t)n * E];
    out[b * E + e] = s * (1.0f / NSEQ);
}

// ---------------- launch -----------------------------------------------------
extern "C" void kernel_launch(void* const* d_in, const int* in_sizes, int n_in,
                              void* d_out, int out_size) {
    const float* x     = (const float*)d_in[0];
    const float* q_w   = (const float*)d_in[1];
    const float* k_w   = (const float*)d_in[2];
    const float* v_w   = (const float*)d_in[3];
    const float* o_w   = (const float*)d_in[4];
    const float* o_b   = (const float*)d_in[5];
    const float* ln1_g = (const float*)d_in[6];
    const float* ln1_b = (const float*)d_in[7];
    const float* ff_w1 = (const float*)d_in[8];
    const float* ff_b1 = (const float*)d_in[9];
    const float* ff_w2 = (const float*)d_in[10];
    const float* ff_b2 = (const float*)d_in[11];
    const float* ln2_g = (const float*)d_in[12];
    const float* ln2_b = (const float*)d_in[13];
    float* out = (float*)d_out;

    float *pt, *py, *pq, *pk, *pv, *po, *pff, *pwt;
    cudaGetSymbolAddress((void**)&pt,  g_t);
    cudaGetSymbolAddress((void**)&py,  g_y);
    cudaGetSymbolAddress((void**)&pq,  g_q);
    cudaGetSymbolAddress((void**)&pk,  g_k);
    cudaGetSymbolAddress((void**)&pv,  g_v);
    cudaGetSymbolAddress((void**)&po,  g_o);
    cudaGetSymbolAddress((void**)&pff, g_ff);
    cudaGetSymbolAddress((void**)&pwt, g_wt);

    cudaFuncSetAttribute(mma_gemm, cudaFuncAttributeMaxDynamicSharedMemorySize, SMEM_TOTAL);

    // prepass: weight convert+transpose (tf32 rna), input transpose
    dim3 tb(32, 8);
    for (int l = 0; l < NLAYERS; l++) {
        float* wl = pwt + (size_t)l * WT_LAYER;
        wt_cvt_kernel<<<dim3(E / 32, E / 32), tb>>>(q_w + (size_t)l * E * E, wl, E, E);
        wt_cvt_kernel<<<dim3(E / 32, E / 32), tb>>>(k_w + (size_t)l * E * E, wl + 16384, E, E);
        wt_cvt_kernel<<<dim3(E / 32, E / 32), tb>>>(v_w + (size_t)l * E * E, wl + 32768, E, E);
        wt_cvt_kernel<<<dim3(E / 32, E / 32), tb>>>(o_w + (size_t)l * E * E, wl + 49152, E, E);
        wt_cvt_kernel<<<dim3(DFF / 32, E / 32), tb>>>(ff_w1 + (size_t)l * E * DFF, wl + 65536, E, DFF);
        wt_cvt_kernel<<<dim3(E / 32, DFF / 32), tb>>>(ff_w2 + (size_t)l * DFF * E, wl + 131072, DFF, E);
    }
    transpose_kernel<<<dim3(NSEQ / 32, E / 32, BATCH), tb>>>(x);

    dim3 gblk(256);
    for (int l = 0; l < NLAYERS; l++) {
        const float* wl = pwt + (size_t)l * WT_LAYER;
        // --- attention block ---
        ln_kernel<<<MROWS, E>>>(ln1_g + l * E, ln1_b + l * E);
        mma_gemm<<<dim3(1, MROWS / GBM), gblk, SMEM_TOTAL>>>(py, wl,          nullptr, pq, E, E, 0);
        mma_gemm<<<dim3(1, MROWS / GBM), gblk, SMEM_TOTAL>>>(py, wl + 16384,  nullptr, pk, E, E, 0);
        mma_gemm<<<dim3(1, MROWS / GBM), gblk, SMEM_TOTAL>>>(py, wl + 32768,  nullptr, pv, E, E, 0);
        softmax_k_kernel<<<BATCH * E, 256>>>();
        ctx_kernel<<<BATCH * NHEADS, 256>>>();
        attn_o_kernel<<<MROWS, E>>>();
        mma_gemm<<<dim3(1, MROWS / GBM), gblk, SMEM_TOTAL>>>(po, wl + 49152,  o_b + l * E, pt, E, E, 2);
        // --- feed-forward block ---
        ln_kernel<<<MROWS, E>>>(ln2_g + l * E, ln2_b + l * E);
        mma_gemm<<<dim3(DFF / GBN, MROWS / GBM), gblk, SMEM_TOTAL>>>(py, wl + 65536, ff_b1 + l * DFF, pff, E, DFF, 1 | 4);
        mma_gemm<<<dim3(1, MROWS / GBM), gblk, SMEM_TOTAL>>>(pff, wl + 131072, ff_b2 + l * E, pt, DFF, E, 2);
    }

    mean_kernel<<<BATCH, E>>>(out);
}

// round 3
// speedup vs baseline: 3.2038x; 1.1943x over previous
#include <cuda_runtime.h>
#include <math.h>
#include <stdint.h>

#define BATCH 64
#define E 128
#define NSEQ 1024
#define NHEADS 8
#define DH 16
#define DFF 512
#define MROWS (BATCH * NSEQ)   // 65536
#define NLAYERS 4
#define LN_EPS 1e-5f
#define QKV_N 384

// ---------------- scratch (static device globals; allocation-free) ----------
__device__ float g_t[MROWS * E];          // residual stream (B, N, E) fp32
__device__ float g_y[MROWS * E];          // layernorm output (tf32-rounded)
__device__ float g_qkv[MROWS * QKV_N];    // fused q|k|v, row stride 384
__device__ float g_o[MROWS * E];          // attention out (tf32-rounded)
__device__ float g_ctx[BATCH * NHEADS * DH * DH];
__device__ float g_ff[MROWS * DFF];       // gelu out (tf32-rounded)
// transposed+tf32 weights per layer: qkv^T(384x128=49152), o^T(16384), ff1^T(65536), ff2^T(65536)
#define WT_LAYER 196608
__device__ float g_wt[NLAYERS * WT_LAYER];

__device__ __forceinline__ float rna_tf32(float x) {
    uint32_t u;
    asm("cvt.rna.tf32.f32 %0, %1;" : "=r"(u) : "f"(x));
    return __uint_as_float(u);
}

__device__ __forceinline__ float gelu_f(float x) {
    float x3 = x * x * x;
    return 0.5f * x * (1.0f + tanhf(0.7978845608028654f * (x + 0.044715f * x3)));
}

// ---------------- transpose x:(B,E,N) -> t:(B,N,E) --------------------------
__global__ void transpose_kernel(const float* __restrict__ x) {
    __shared__ float tile[32][33];
    int b  = blockIdx.z;
    int n0 = blockIdx.x * 32;
    int e0 = blockIdx.y * 32;
    int tx = threadIdx.x, ty = threadIdx.y;   // (32,8)
#pragma unroll
    for (int i = 0; i < 32; i += 8)
        tile[ty + i][tx] = x[(size_t)b * E * NSEQ + (size_t)(e0 + ty + i) * NSEQ + n0 + tx];
    __syncthreads();
#pragma unroll
    for (int i = 0; i < 32; i += 8)
        g_t[(size_t)b * NSEQ * E + (size_t)(n0 + ty + i) * E + e0 + tx] = tile[tx][ty + i];
}

// ---------------- weight convert: src[K][N] -> dst[N][K], tf32 rna ----------
__global__ void wt_cvt_kernel(const float* __restrict__ src, float* __restrict__ dst,
                              int K, int N) {
    __shared__ float tile[32][33];
    int n0 = blockIdx.x * 32;
    int k0 = blockIdx.y * 32;
    int tx = threadIdx.x, ty = threadIdx.y;   // (32,8)
#pragma unroll
    for (int i = 0; i < 32; i += 8)
        tile[ty + i][tx] = src[(size_t)(k0 + ty + i) * N + n0 + tx];
    __syncthreads();
#pragma unroll
    for (int i = 0; i < 32; i += 8)
        dst[(size_t)(n0 + ty + i) * K + k0 + tx] = rna_tf32(tile[tx][ty + i]);
}

// ---------------- standalone layernorm (layer-0 entry only) -----------------
__global__ void ln_kernel(const float* __restrict__ gamma, const float* __restrict__ beta) {
    int m = blockIdx.x;
    int e = threadIdx.x;
    float v = g_t[(size_t)m * E + e];

    __shared__ float red[4];
    float s = v;
#pragma unroll
    for (int o = 16; o > 0; o >>= 1) s += __shfl_down_sync(0xffffffffu, s, o);
    if ((e & 31) == 0) red[e >> 5] = s;
    __syncthreads();
    float mu = (red[0] + red[1] + red[2] + red[3]) * (1.0f / E);
    __syncthreads();

    float d = v - mu;
    float s2 = d * d;
#pragma unroll
    for (int o = 16; o > 0; o >>= 1) s2 += __shfl_down_sync(0xffffffffu, s2, o);
    if ((e & 31) == 0) red[e >> 5] = s2;
    __syncthreads();
    float var = (red[0] + red[1] + red[2] + red[3]) * (1.0f / E);

    g_y[(size_t)m * E + e] = rna_tf32(d * rsqrtf(var + LN_EPS) * gamma[e] + beta[e]);
}

// ---------------- TF32 tensor-core GEMM, 3-stage pipeline -------------------
// C[M,N] = op(A[M,K] @ Wt[N,K]^T + bias) (+C residual)
// flags: 1=gelu, 2=residual add, 4=tf32-round C, 8=fused LN -> Y (requires N=128, grid.x=1)
#define GBM 128
#define GBN 128
#define GBK 32
#define NSTAGE 3
#define STAGE_BYTES 16384          // 128*32*4
#define BSMEM_OFF (NSTAGE * STAGE_BYTES)
#define SMEM_BYTES (2 * NSTAGE * STAGE_BYTES)   // 98304

#define LDSM4(d0, d1, d2, d3, addr) \
    asm volatile("ldmatrix.sync.aligned.m8n8.x4.shared.b16 {%0,%1,%2,%3}, [%4];" \
                 : "=r"(d0), "=r"(d1), "=r"(d2), "=r"(d3) : "r"(addr))

#define MMA_TF32(c, a, b) \
    asm volatile("mma.sync.aligned.m16n8k8.row.col.f32.tf32.tf32.f32 " \
                 "{%0,%1,%2,%3},{%4,%5,%6,%7},{%8,%9},{%0,%1,%2,%3};" \
                 : "+f"((c)[0]), "+f"((c)[1]), "+f"((c)[2]), "+f"((c)[3]) \
                 : "r"((a)[0]), "r"((a)[1]), "r"((a)[2]), "r"((a)[3]), \
                   "r"((b)[0]), "r"((b)[1]))

__device__ __forceinline__ void cp_async16(uint32_t dst, const void* src) {
    asm volatile("cp.async.cg.shared.global [%0], [%1], 16;" :: "r"(dst), "l"(src));
}

__global__ __launch_bounds__(256, 2) void mma_gemm(
    const float* __restrict__ A, const float* __restrict__ Wt,
    const float* __restrict__ bias, float* __restrict__ C,
    const float* __restrict__ gamma, const float* __restrict__ beta,
    float* __restrict__ Y,
    int K, int N, int flags)
{
    extern __shared__ float sm[];
    uint32_t smem_u = (uint32_t)__cvta_generic_to_shared(sm);

    int tid  = threadIdx.x;
    int lane = tid & 31;
    int wid  = tid >> 5;
    int warp_m = wid & 1;            // 2 x 64-row slabs
    int warp_n = wid >> 1;           // 4 x 32-col slabs
    int bm0 = blockIdx.y * GBM;
    int bn0 = blockIdx.x * GBN;

    int r0 = tid >> 3;               // row (0..31)
    int c8 = tid & 7;                // 16B chunk in row
    uint32_t cxor = (uint32_t)((c8 ^ (r0 & 7)) << 4);

    int sub = lane >> 3;
    int l7  = lane & 7;
    int selA = sub >> 1;
    int rowAoff = ((sub & 1) << 3) + l7;
    int selB = sub & 1;
    int rowBoff = ((sub >> 1) << 3) + l7;

    float acc[4][4][4];
#pragma unroll
    for (int i = 0; i < 4; i++)
#pragma unroll
        for (int j = 0; j < 4; j++)
#pragma unroll
            for (int k = 0; k < 4; k++) acc[i][j][k] = 0.f;

    int nIter = K >> 5;              // >= 4 always

    auto load_tile = [&](int s, int k0) {
#pragma unroll
        for (int i = 0; i < 4; i++) {
            int r = r0 + i * 32;
            uint32_t doff = (uint32_t)(r << 7) + cxor;
            const float* pa = A  + (size_t)(bm0 + r) * K + k0 + c8 * 4;
            const float* pb = Wt + (size_t)(bn0 + r) * K + k0 + c8 * 4;
            cp_async16(smem_u + s * STAGE_BYTES + doff, pa);
            cp_async16(smem_u + BSMEM_OFF + s * STAGE_BYTES + doff, pb);
        }
    };

    load_tile(0, 0);
    asm volatile("cp.async.commit_group;");
    load_tile(1, GBK);
    asm volatile("cp.async.commit_group;");

    for (int it = 0; it < nIter; it++) {
        if (it < nIter - 1) asm volatile("cp.async.wait_group 1;");
        else                asm volatile("cp.async.wait_group 0;");
        __syncthreads();

        int s = it % NSTAGE;
        uint32_t baseA = smem_u + s * STAGE_BYTES;
        uint32_t baseB = smem_u + BSMEM_OFF + s * STAGE_BYTES;

#pragma unroll
        for (int ks = 0; ks < 4; ks++) {
            int cb = ks * 2;
            uint32_t a[4][4], b[4][2];
#pragma unroll
            for (int mt = 0; mt < 4; mt++) {
                int row = warp_m * 64 + mt * 16 + rowAoff;
                uint32_t addr = baseA + (row << 7) + (uint32_t)(((cb + selA) ^ (row & 7)) << 4);
                LDSM4(a[mt][0], a[mt][1], a[mt][2], a[mt][3], addr);
            }
#pragma unroll
            for (int bt = 0; bt < 2; bt++) {
                int row = warp_n * 32 + bt * 16 + rowBoff;
                uint32_t addr = baseB + (row << 7) + (uint32_t)(((cb + selB) ^ (row & 7)) << 4);
                LDSM4(b[2 * bt][0], b[2 * bt][1], b[2 * bt + 1][0], b[2 * bt + 1][1], addr);
            }
#pragma unroll
            for (int mt = 0; mt < 4; mt++)
#pragma unroll
                for (int nt = 0; nt < 4; nt++)
                    MMA_TF32(acc[mt][nt], a[mt], b[nt]);
        }

        if (it + 2 < nIter) {
            load_tile((it + 2) % NSTAGE, (it + 2) * GBK);
            asm volatile("cp.async.commit_group;");
        }
    }

    // ---- epilogue ----
    int g  = lane >> 2;
    int t4 = lane & 3;
    bool do_ln = (flags & 8) != 0;
    if (do_ln) __syncthreads();      // all warps done with pipeline smem

#pragma unroll
    for (int mt = 0; mt < 4; mt++) {
        int rowl0 = warp_m * 64 + mt * 16 + g;
#pragma unroll
        for (int nt = 0; nt < 4; nt++) {
            int coll = warp_n * 32 + nt * 8 + t4 * 2;
            int col  = bn0 + coll;
            float v[4] = { acc[mt][nt][0], acc[mt][nt][1], acc[mt][nt][2], acc[mt][nt][3] };
            if (bias) {
                float b0 = bias[col], b1 = bias[col + 1];
                v[0] += b0; v[1] += b1; v[2] += b0; v[3] += b1;
            }
            if (flags & 1) {
#pragma unroll
                for (int z = 0; z < 4; z++) v[z] = gelu_f(v[z]);
            }
            if (flags & 4) {
#pragma unroll
                for (int z = 0; z < 4; z++) v[z] = rna_tf32(v[z]);
            }
#pragma unroll
            for (int half = 0; half < 2; half++) {
                int rowl = rowl0 + half * 8;
                float2* p = (float2*)(C + (size_t)(bm0 + rowl) * N + col);
                float f0 = v[half * 2], f1 = v[half * 2 + 1];
                if (flags & 2) {
                    float2 o = *p;
                    f0 += o.x; f1 += o.y;
                }
                *p = make_float2(f0, f1);
                if (do_ln) {
                    sm[rowl * 132 + coll]     = f0;
                    sm[rowl * 132 + coll + 1] = f1;
                }
            }
        }
    }

    if (do_ln) {
        __syncthreads();
        float g4[4], b4[4];
#pragma unroll
        for (int j = 0; j < 4; j++) {
            g4[j] = gamma[lane + 32 * j];
            b4[j] = beta[lane + 32 * j];
        }
        for (int r = 0; r < 16; r++) {
            int row = wid * 16 + r;
            float x[4];
#pragma unroll
            for (int j = 0; j < 4; j++) x[j] = sm[row * 132 + lane + 32 * j];
            float s = x[0] + x[1] + x[2] + x[3];
#pragma unroll
            for (int o = 16; o > 0; o >>= 1) s += __shfl_xor_sync(0xffffffffu, s, o);
            float mu = s * (1.0f / E);
            float s2 = 0.f;
#pragma unroll
            for (int j = 0; j < 4; j++) { float d = x[j] - mu; s2 += d * d; }
#pragma unroll
            for (int o = 16; o > 0; o >>= 1) s2 += __shfl_xor_sync(0xffffffffu, s2, o);
            float rs = rsqrtf(s2 * (1.0f / E) + LN_EPS);
#pragma unroll
            for (int j = 0; j < 4; j++)
                Y[(size_t)(bm0 + row) * E + lane + 32 * j] =
                    rna_tf32((x[j] - mu) * rs * g4[j] + b4[j]);
        }
    }
}

// ---------------- fused softmax_k + ctx per (b,h) ---------------------------
__global__ void ctx_kernel() {
    int bh = blockIdx.x;              // b*8 + h
    int b = bh >> 3, h = bh & 7;
    const float* kbase = g_qkv + (size_t)b * NSEQ * QKV_N + E + h * DH;
    const float* vbase = kbase + E;   // v section
    int tid = threadIdx.x;            // 256

    // pass A: column-wise max over sequence
    __shared__ float smax[16][17];
    __shared__ float mx[16];
    int d0 = tid & 15, i0 = tid >> 4;
    float m = -1e30f;
    for (int i = 0; i < 64; i++) {
        int n = i0 + i * 16;
        m = fmaxf(m, kbase[(size_t)n * QKV_N + d0]);
    }
    smax[d0][i0] = m;
    __syncthreads();
    if (tid < 16) {
        float t = smax[tid][0];
#pragma unroll
        for (int i = 1; i < 16; i++) t = fmaxf(t, smax[tid][i]);
        mx[tid] = t;
    }
    __syncthreads();

    // pass B: accumulate exp(k)-weighted v and exp-sums
    __shared__ float ks[128][17];
    __shared__ float vs[128][17];
    int d = tid >> 4, e = tid & 15;
    float acc = 0.f, ssum = 0.f;
    for (int n0 = 0; n0 < NSEQ; n0 += 128) {
        __syncthreads();
        for (int l = tid; l < 128 * 16; l += 256) {
            int nl = l >> 4, c = l & 15;
            ks[nl][c] = expf(kbase[(size_t)(n0 + nl) * QKV_N + c] - mx[c]);
            vs[nl][c] = vbase[(size_t)(n0 + nl) * QKV_N + c];
        }
        __syncthreads();
#pragma unroll 8
        for (int nl = 0; nl < 128; nl++) {
            float kk = ks[nl][d];
            acc += kk * vs[nl][e];
            ssum += kk;
        }
    }
    g_ctx[bh * 256 + d * 16 + e] = acc / ssum;
}

// ---------------- o = softmax_q(q) @ ctx (fused), tf32-rounded --------------
__global__ void attn_o_kernel() {
    int m = blockIdx.x;
    int e = threadIdx.x;              // 0..127
    int h = e >> 4, el = e & 15;
    int b = m >> 10;
    const float* qp = g_qkv + (size_t)m * QKV_N + h * DH;
    float qv[DH];
    float mx = -1e30f;
#pragma unroll
    for (int d = 0; d < DH; d++) { qv[d] = qp[d]; mx = fmaxf(mx, qv[d]); }
    float s = 0.f;
#pragma unroll
    for (int d = 0; d < DH; d++) { qv[d] = expf(qv[d] - mx); s += qv[d]; }
    float r = 0.25f / s;   // dh^-0.5 = 0.25
    const float* cp = g_ctx + (b * NHEADS + h) * 256 + el;
    float acc = 0.f;
#pragma unroll
    for (int d = 0; d < DH; d++) acc += qv[d] * cp[d * 16];
    g_o[(size_t)m * E + e] = rna_tf32(acc * r);
}

// ---------------- final mean over sequence ----------------------------------
__global__ void mean_kernel(float* __restrict__ out) {
    int b = blockIdx.x, e = threadIdx.x;
    const float* p = g_t + (size_t)b * NSEQ * E + e;
    float s = 0.f;
#pragma unroll 8
    for (int n = 0; n < NSEQ; n++) s += p[(size_t)n * E];
    out[b * E + e] = s * (1.0f / NSEQ);
}

// ---------------- launch -----------------------------------------------------
extern "C" void kernel_launch(void* const* d_in, const int* in_sizes, int n_in,
                              void* d_out, int out_size) {
    const float* x     = (const float*)d_in[0];
    const float* q_w   = (const float*)d_in[1];
    const float* k_w   = (const float*)d_in[2];
    const float* v_w   = (const float*)d_in[3];
    const float* o_w   = (const float*)d_in[4];
    const float* o_b   = (const float*)d_in[5];
    const float* ln1_g = (const float*)d_in[6];
    const float* ln1_b = (const float*)d_in[7];
    const float* ff_w1 = (const float*)d_in[8];
    const float* ff_b1 = (const float*)d_in[9];
    const float* ff_w2 = (const float*)d_in[10];
    const float* ff_b2 = (const float*)d_in[11];
    const float* ln2_g = (const float*)d_in[12];
    const float* ln2_b = (const float*)d_in[13];
    float* out = (float*)d_out;

    float *pt, *py, *pqkv, *po, *pff, *pwt;
    cudaGetSymbolAddress((void**)&pt,   g_t);
    cudaGetSymbolAddress((void**)&py,   g_y);
    cudaGetSymbolAddress((void**)&pqkv, g_qkv);
    cudaGetSymbolAddress((void**)&po,   g_o);
    cudaGetSymbolAddress((void**)&pff,  g_ff);
    cudaGetSymbolAddress((void**)&pwt,  g_wt);

    cudaFuncSetAttribute(mma_gemm, cudaFuncAttributeMaxDynamicSharedMemorySize, SMEM_BYTES);

    // prepass: weight convert+transpose (tf32 rna), input transpose
    dim3 tb(32, 8);
    for (int l = 0; l < NLAYERS; l++) {
        float* wl = pwt + (size_t)l * WT_LAYER;
        wt_cvt_kernel<<<dim3(E / 32, E / 32), tb>>>(q_w + (size_t)l * E * E, wl, E, E);
        wt_cvt_kernel<<<dim3(E / 32, E / 32), tb>>>(k_w + (size_t)l * E * E, wl + 16384, E, E);
        wt_cvt_kernel<<<dim3(E / 32, E / 32), tb>>>(v_w + (size_t)l * E * E, wl + 32768, E, E);
        wt_cvt_kernel<<<dim3(E / 32, E / 32), tb>>>(o_w + (size_t)l * E * E, wl + 49152, E, E);
        wt_cvt_kernel<<<dim3(DFF / 32, E / 32), tb>>>(ff_w1 + (size_t)l * E * DFF, wl + 65536, E, DFF);
        wt_cvt_kernel<<<dim3(E / 32, DFF / 32), tb>>>(ff_w2 + (size_t)l * DFF * E, wl + 131072, DFF, E);
    }
    transpose_kernel<<<dim3(NSEQ / 32, E / 32, BATCH), tb>>>(x);

    // layer-0 entry LN
    ln_kernel<<<MROWS, E>>>(ln1_g, ln1_b);

    dim3 gblk(256);
    for (int l = 0; l < NLAYERS; l++) {
        const float* wl = pwt + (size_t)l * WT_LAYER;
        // fused QKV GEMM: y @ [q|k|v]  (N=384)
        mma_gemm<<<dim3(QKV_N / GBN, MROWS / GBM), gblk, SMEM_BYTES>>>(
            py, wl, nullptr, pqkv, nullptr, nullptr, nullptr, E, QKV_N, 0);
        // fused softmax_k + ctx, then fused softmax_q + o
        ctx_kernel<<<BATCH * NHEADS, 256>>>();
        attn_o_kernel<<<MROWS, E>>>();
        // o-proj GEMM + residual + fused LN2 -> y
        mma_gemm<<<dim3(1, MROWS / GBM), gblk, SMEM_BYTES>>>(
            po, wl + 49152, o_b + l * E, pt, ln2_g + l * E, ln2_b + l * E, py, E, E, 2 | 8);
        // FF1 + gelu (tf32-rounded)
        mma_gemm<<<dim3(DFF / GBN, MROWS / GBM), gblk, SMEM_BYTES>>>(
            py, wl + 65536, ff_b1 + l * DFF, pff, nullptr, nullptr, nullptr, E, DFF, 1 | 4);
        // FF2 + residual (+ fused LN1 of next layer, except last)
        if (l < NLAYERS - 1) {
            mma_gemm<<<dim3(1, MROWS / GBM), gblk, SMEM_BYTES>>>(
                pff, wl + 131072, ff_b2 + l * E, pt,
                ln1_g + (l + 1) * E, ln1_b + (l + 1) * E, py, DFF, E, 2 | 8);
        } else {
            mma_gemm<<<dim3(1, MROWS / GBM), gblk, SMEM_BYTES>>>(
                pff, wl + 131072, ff_b2 + l * E, pt,
                nullptr, nullptr, nullptr, DFF, E, 2);
        }
    }

    mean_kernel<<<BATCH, E>>>(out);
}